// round 11
// baseline (speedup 1.0000x reference)
#include <cuda_runtime.h>
#include <math.h>

// ---------------------------------------------------------------------------
// Constants: B=2, DIM=256, H=W=64, HEADS=8, HC=32, HG=2, GC=128,
// STRIDE=2 -> RH=RW=32, R=1024 ; WS=8 -> WH=WW=8, NW=64, WT=64 ; MLP_HID=1024
// ---------------------------------------------------------------------------

__device__ float g_xa[2097152];     // [2][256][4096]
__device__ float g_q[2097152];      // [2][256][4096]
__device__ float g_o1[524288];      // dw1 out; reused for off [4][2048][64]
__device__ float g_o2[131072];      // [4][128][16*16]
__device__ float g_o3[32768];       // [4][128][64]
__device__ float g_grid[524288];    // [4][64][1024][2]  (row_pix, col_pix)
__device__ float g_kpart[4194304];  // [4][4096][256] pixel-major
__device__ float g_vpart[4194304];
__device__ float g_attno[2097152];  // [2][256][4096]
__device__ float g_y1[2097152];
__device__ float g_xm[2097152];
__device__ float g_hdn[8388608];    // [2][1024][4096]

__device__ __forceinline__ float gelu_f(float v) {
    return 0.5f * v * (1.0f + erff(v * 0.70710678118654752440f));
}

__device__ __forceinline__ unsigned tf32_of(float f) {
    unsigned u;
    asm("cvt.rna.tf32.f32 %0, %1;" : "=r"(u) : "f"(f));
    return u;
}

// ---------------------------------------------------------------------------
// LayerNorm over 256 channels per pixel. Block = 32 pixels, 8 warps.
// ---------------------------------------------------------------------------
__global__ __launch_bounds__(256) void ln2d_kernel(
    const float* __restrict__ x, const float* __restrict__ g,
    const float* __restrict__ bt, float* __restrict__ out)
{
    int lane = threadIdx.x & 31, wz = threadIdx.x >> 5;
    int pix = blockIdx.x * 32 + lane;
    int b = pix >> 12, p = pix & 4095;
    const float* xb = x + (size_t)b * 1048576 + p;
    float v[32];
    float s = 0.f, sq = 0.f;
#pragma unroll
    for (int i = 0; i < 32; i++) {
        int c = wz + i * 8;
        float t = xb[(size_t)c * 4096];
        v[i] = t; s += t; sq += t * t;
    }
    __shared__ float ssum[8][33], ssq[8][33];
    __shared__ float smu[32], srs[32];
    ssum[wz][lane] = s; ssq[wz][lane] = sq;
    __syncthreads();
    if (wz == 0) {
        float S = 0.f, Q = 0.f;
#pragma unroll
        for (int i = 0; i < 8; i++) { S += ssum[i][lane]; Q += ssq[i][lane]; }
        float mu = S * (1.f / 256.f);
        float var = Q * (1.f / 256.f) - mu * mu;
        smu[lane] = mu;
        srs[lane] = rsqrtf(var + 1e-5f);
    }
    __syncthreads();
    float mu = smu[lane], rs = srs[lane];
    float* ob = out + (size_t)b * 1048576 + p;
#pragma unroll
    for (int i = 0; i < 32; i++) {
        int c = wz + i * 8;
        ob[(size_t)c * 4096] = (v[i] - mu) * rs * g[c] + bt[c];
    }
}

// ---------------------------------------------------------------------------
// TF32 tensor-core GEMM: C[m][n] = sum_k A[m*lda+k] * B[k*N+n]
// Tile 64x64, K-chunk 16, 256 threads (8 warps), mma.sync.m16n8k8.
// flags: 1=bias 2=gelu 4=residual 8=transpose_out
// ---------------------------------------------------------------------------
__global__ __launch_bounds__(256) void sgemm_kernel(
    const float* __restrict__ A, const float* __restrict__ B, float* __restrict__ C,
    const float* __restrict__ bias, const float* __restrict__ res,
    int M, int N, int K, int lda,
    long long strideB, long long strideC, long long strideRes, int flags)
{
    int bz = blockIdx.z;
    B += (long long)bz * strideB;
    C += (long long)bz * strideC;
    if (res) res += (long long)bz * strideRes;

    int m0 = blockIdx.y * 64, n0 = blockIdx.x * 64;
    __shared__ unsigned As[16][72];   // As[k][m]  (tf32 bits)
    __shared__ unsigned Bs[16][72];   // Bs[k][n]  (tf32 bits)
    int tid = threadIdx.x;
    int lane = tid & 31, warp = tid >> 5;
    int la_m = tid >> 4, la_k = tid & 15;
    int lb_k = tid >> 6, lb_n = tid & 63;

    int g = lane >> 2, tg = lane & 3;      // fragment coords
    int mrow = (warp & 3) * 16;
    int ncol = (warp >> 2) * 32;

    float d[4][4];
#pragma unroll
    for (int j = 0; j < 4; j++)
#pragma unroll
        for (int i = 0; i < 4; i++) d[j][i] = 0.f;

    for (int k0 = 0; k0 < K; k0 += 16) {
#pragma unroll
        for (int r = 0; r < 4; r++)
            As[la_k][la_m + 16 * r] = tf32_of(A[(size_t)(m0 + la_m + 16 * r) * lda + k0 + la_k]);
#pragma unroll
        for (int r = 0; r < 4; r++)
            Bs[lb_k + 4 * r][lb_n] = tf32_of(B[(size_t)(k0 + lb_k + 4 * r) * N + n0 + lb_n]);
        __syncthreads();

#pragma unroll
        for (int ks = 0; ks < 16; ks += 8) {
            unsigned a0 = As[ks + tg][mrow + g];
            unsigned a1 = As[ks + tg][mrow + g + 8];
            unsigned a2 = As[ks + tg + 4][mrow + g];
            unsigned a3 = As[ks + tg + 4][mrow + g + 8];
#pragma unroll
            for (int j = 0; j < 4; j++) {
                unsigned b0 = Bs[ks + tg][ncol + 8 * j + g];
                unsigned b1 = Bs[ks + tg + 4][ncol + 8 * j + g];
                asm volatile(
                    "mma.sync.aligned.m16n8k8.row.col.f32.tf32.tf32.f32 "
                    "{%0,%1,%2,%3}, {%4,%5,%6,%7}, {%8,%9}, {%0,%1,%2,%3};\n"
                    : "+f"(d[j][0]), "+f"(d[j][1]), "+f"(d[j][2]), "+f"(d[j][3])
                    : "r"(a0), "r"(a1), "r"(a2), "r"(a3), "r"(b0), "r"(b1));
            }
        }
        __syncthreads();
    }

#pragma unroll
    for (int half = 0; half < 2; half++) {
        int m = m0 + mrow + g + half * 8;
        float bv = (flags & 1) ? bias[m] : 0.f;
#pragma unroll
        for (int j = 0; j < 4; j++) {
#pragma unroll
            for (int e = 0; e < 2; e++) {
                int n = n0 + ncol + 8 * j + 2 * tg + e;
                float v = d[j][half * 2 + e] + bv;
                if (flags & 2) v = gelu_f(v);
                if (flags & 4) v += res[(size_t)m * N + n];
                if (flags & 8) C[(size_t)n * M + m] = v;
                else           C[(size_t)m * N + n] = v;
            }
        }
    }
}

// ---------------------------------------------------------------------------
// Depthwise 3x3 stride-2 pad-1 conv; optional BN + exact GELU.
// ---------------------------------------------------------------------------
__global__ __launch_bounds__(256) void dwconv_kernel(
    const float* __restrict__ in, const float* __restrict__ w9, float* __restrict__ out,
    int Hi, int Ho, int do_bn,
    const float* __restrict__ bn_g, const float* __restrict__ bn_b,
    const float* __restrict__ bn_m, const float* __restrict__ bn_v)
{
    int bc = blockIdx.x;
    int c = bc & 127;
    const float* ip = in + (size_t)bc * Hi * Hi;
    float* op = out + (size_t)bc * Ho * Ho;
    float wv[9];
#pragma unroll
    for (int i = 0; i < 9; i++) wv[i] = w9[c * 9 + i];
    float bg = 0.f, bb = 0.f, bm = 0.f, brs = 1.f;
    if (do_bn) {
        bg = bn_g[c]; bb = bn_b[c]; bm = bn_m[c];
        brs = rsqrtf(bn_v[c] + 1e-5f);
    }
    for (int idx = threadIdx.x; idx < Ho * Ho; idx += blockDim.x) {
        int oy = idx / Ho, ox = idx - oy * Ho;
        int iy0 = oy * 2 - 1, ix0 = ox * 2 - 1;
        float s = 0.f;
#pragma unroll
        for (int ki = 0; ki < 3; ki++) {
            int iy = iy0 + ki;
            if (iy < 0 || iy >= Hi) continue;
#pragma unroll
            for (int kj = 0; kj < 3; kj++) {
                int ix = ix0 + kj;
                if (ix < 0 || ix >= Hi) continue;
                s += ip[iy * Hi + ix] * wv[ki * 3 + kj];
            }
        }
        if (do_bn) {
            s = (s - bm) * brs * bg + bb;
            s = gelu_f(s);
        }
        op[idx] = s;
    }
}

// ---------------------------------------------------------------------------
// Build sampling grid in PIXEL coords. off: [4][2048][64], grid: [4][64][1024][2]
// ---------------------------------------------------------------------------
__global__ __launch_bounds__(256) void grid_kernel(
    const float* __restrict__ off, float* __restrict__ grid)
{
    int idx = blockIdx.x * 256 + threadIdx.x;       // 0 .. 524287
    int d = idx & 1;
    int r = (idx >> 1) & 1023;
    int w = (idx >> 11) & 63;
    int bg = idx >> 17;
    float v = tanhf(off[((size_t)bg * 2048 + d * 1024 + r) * 64 + w]);
    int i = d ? (r & 31) : (r >> 5);
    float ref = 4.0f * (float)i / 63.0f - 1.0f;
    grid[idx] = (v * 0.03125f + ref + 1.0f) * 31.5f;
}

// ---------------------------------------------------------------------------
// Fused sampling + windowed deformable attention (flash-style, fp32 SIMT).
// Block per (b, head, w): 256 threads = 8 warps, warp owns 8 queries.
// K/V tiles are gathered on the fly from kpart/vpart (32-ch head slice,
// bilinear taps from BOTH group grids) — no kk/vv materialization.
// ---------------------------------------------------------------------------
__global__ __launch_bounds__(256) void attn_kernel(
    const float* __restrict__ q,
    const float* __restrict__ kpart, const float* __restrict__ vpart,
    const float* __restrict__ grid,
    const float* __restrict__ k_b, const float* __restrict__ v_b,
    const float* __restrict__ posembed,
    float* __restrict__ attno)
{
    int blk = blockIdx.x;
    int w = blk & 63, head = (blk >> 6) & 7, b = blk >> 9;
    int wh = w >> 3, ww = w & 7;
    int tid = threadIdx.x;
    int lane = tid & 31, warp = tid >> 5;
    int cbase = head * 32;

    extern __shared__ float sm[];
    float* Qs  = sm;                 // [64][33]   = 2112
    float* pes = Qs + 2112;          // [70][71]   = 4970, padded to 4972
    float* Ks  = pes + 4972;         // [32][132]  = 4224
    float* Vs  = Ks + 4224;          // [128][36]  = 4608  (base 11308 -> 16B aligned)
    float* Ss  = Vs + 4608;          // [64][132]  = 8448
    float* bias_s = Ss + 8448;       // [64]  (K bias 0..31, V bias 32..63)
    // total 24428 floats = 97712 bytes

    // Load Q (scaled by C^-0.5 = 1/16)
    {
        const float* qb = q + (size_t)b * 1048576 + (size_t)cbase * 4096;
        int c = tid >> 3, t0 = tid & 7;
#pragma unroll
        for (int tr = 0; tr < 8; tr++) {
            int t = tr * 8 + t0;
            int pix = (wh * 8 + tr) * 64 + ww * 8 + t0;
            Qs[t * 33 + c] = qb[(size_t)c * 4096 + pix] * 0.0625f;
        }
    }
    // Biases for this head slice
    if (tid < 32) bias_s[tid] = k_b[cbase + tid];
    else if (tid < 64) bias_s[tid] = v_b[cbase + tid - 32];
    // Load posembed patch: rows [56-8wh, +70), cols [56-8ww, +70)
    {
        int row0 = 56 - wh * 8, col0 = 56 - ww * 8;
        const float* pe = posembed + (size_t)head * 16129;
        for (int idx = tid; idx < 4900; idx += 256) {
            int i = idx / 70, j = idx - i * 70;
            pes[i * 71 + j] = pe[(row0 + i) * 127 + col0 + j];
        }
    }

    float m_i[8], l_i[8], o_acc[8];
#pragma unroll
    for (int i = 0; i < 8; i++) { m_i[i] = -1e30f; l_i[i] = 0.f; o_acc[i] = 0.f; }
    int qbase = warp * 8;

    for (int rt = 0; rt < 1024; rt += 128) {
        __syncthreads();
        // Gather one K row (threads 0-127) or V row (threads 128-255):
        // 32 channels = bilinear taps from both group grids.
        {
            int r = tid & 127, tensor = tid >> 7;
            int rg = rt + r;
            float acc[32];
#pragma unroll
            for (int c = 0; c < 32; c++) acc[c] = 0.f;
            const float* base = tensor ? vpart : kpart;
#pragma unroll
            for (int g2 = 0; g2 < 2; g2++) {
                int bg = b * 2 + g2;
                const float* gp = grid + (((size_t)bg * 64 + w) * 1024 + rg) * 2;
                float row = gp[0], col = gp[1];
                float r0f = floorf(row), c0f = floorf(col);
                float wr = row - r0f, wc = col - c0f;
                int r0 = (int)r0f, c0 = (int)c0f;
                const float* src = base + (size_t)bg * 1048576 + cbase;
#pragma unroll
                for (int t = 0; t < 4; t++) {
                    int ri = r0 + (t >> 1), ci = c0 + (t & 1);
                    float wt = ((t >> 1) ? wr : 1.0f - wr) * ((t & 1) ? wc : 1.0f - wc);
                    if (ri >= 0 && ri < 64 && ci >= 0 && ci < 64) {
                        const float4* p = (const float4*)(src + (size_t)(ri * 64 + ci) * 256);
#pragma unroll
                        for (int qd = 0; qd < 8; qd++) {
                            float4 v4 = p[qd];
                            acc[qd * 4 + 0] += wt * v4.x;
                            acc[qd * 4 + 1] += wt * v4.y;
                            acc[qd * 4 + 2] += wt * v4.z;
                            acc[qd * 4 + 3] += wt * v4.w;
                        }
                    }
                }
            }
            if (tensor == 0) {
#pragma unroll
                for (int c = 0; c < 32; c++) Ks[c * 132 + r] = acc[c] + bias_s[c];
            } else {
#pragma unroll
                for (int c4 = 0; c4 < 32; c4 += 4) {
                    float4 v4;
                    v4.x = acc[c4 + 0] + bias_s[32 + c4 + 0];
                    v4.y = acc[c4 + 1] + bias_s[32 + c4 + 1];
                    v4.z = acc[c4 + 2] + bias_s[32 + c4 + 2];
                    v4.w = acc[c4 + 3] + bias_s[32 + c4 + 3];
                    *(float4*)(Vs + r * 36 + c4) = v4;
                }
            }
        }
        __syncthreads();

        // S = Q K^T : thread owns (qbase+i, lane+32j)
        float s[8][4];
#pragma unroll
        for (int i = 0; i < 8; i++)
#pragma unroll
            for (int j = 0; j < 4; j++) s[i][j] = 0.f;
#pragma unroll 4
        for (int c = 0; c < 32; c++) {
            float kv[4];
#pragma unroll
            for (int j = 0; j < 4; j++) kv[j] = Ks[c * 132 + lane + 32 * j];
#pragma unroll
            for (int i = 0; i < 8; i++) {
                float qv = Qs[(qbase + i) * 33 + c];
#pragma unroll
                for (int j = 0; j < 4; j++) s[i][j] += qv * kv[j];
            }
        }
        // + relative position bias from pe patch
#pragma unroll
        for (int i = 0; i < 8; i++) {
            int qq = qbase + i; int tr = qq >> 3, tc = qq & 7;
#pragma unroll
            for (int j = 0; j < 4; j++) {
                int r = rt + lane + 32 * j;
                int ry = r >> 5, rx = r & 31;
                s[i][j] += pes[(2 * ry - tr + 7) * 71 + (2 * rx - tc + 7)];
            }
        }
        // Online softmax per query
#pragma unroll
        for (int i = 0; i < 8; i++) {
            float mx = s[i][0];
#pragma unroll
            for (int j = 1; j < 4; j++) mx = fmaxf(mx, s[i][j]);
#pragma unroll
            for (int off = 16; off > 0; off >>= 1)
                mx = fmaxf(mx, __shfl_xor_sync(0xffffffffu, mx, off));
            float mnew = fmaxf(m_i[i], mx);
            float corr = __expf(m_i[i] - mnew);
            m_i[i] = mnew;
            float psum = 0.f;
            float p4[4];
#pragma unroll
            for (int j = 0; j < 4; j++) {
                p4[j] = __expf(s[i][j] - mnew);
                psum += p4[j];
            }
#pragma unroll
            for (int off = 16; off > 0; off >>= 1)
                psum += __shfl_xor_sync(0xffffffffu, psum, off);
            l_i[i] = l_i[i] * corr + psum;
            o_acc[i] *= corr;
#pragma unroll
            for (int j = 0; j < 4; j++)
                Ss[(qbase + i) * 132 + lane + 32 * j] = p4[j];
        }
        __syncwarp();
        // O += P V : thread owns column c=lane for queries qbase..qbase+7
#pragma unroll 2
        for (int rl = 0; rl < 128; rl++) {
            float v = Vs[rl * 36 + lane];
#pragma unroll
            for (int i = 0; i < 8; i++)
                o_acc[i] += Ss[(qbase + i) * 132 + rl] * v;
        }
        __syncwarp();
    }

    // Write attno[b][cbase+lane][pix]
    float* ao = attno + (size_t)b * 1048576 + (size_t)(cbase + lane) * 4096;
#pragma unroll
    for (int i = 0; i < 8; i++) {
        int qq = qbase + i; int tr = qq >> 3, tc = qq & 7;
        int pix = (wh * 8 + tr) * 64 + ww * 8 + tc;
        ao[pix] = o_acc[i] / l_i[i];
    }
}

// ---------------------------------------------------------------------------
// Host launcher
// ---------------------------------------------------------------------------
extern "C" void kernel_launch(void* const* d_in, const int* in_sizes, int n_in,
                              void* d_out, int out_size)
{
    const float* x       = (const float*)d_in[0];
    const float* ln1_g   = (const float*)d_in[1];
    const float* ln1_b   = (const float*)d_in[2];
    const float* q_w     = (const float*)d_in[3];
    const float* q_b     = (const float*)d_in[4];
    const float* k_w     = (const float*)d_in[5];
    const float* k_b     = (const float*)d_in[6];
    const float* v_w     = (const float*)d_in[7];
    const float* v_b     = (const float*)d_in[8];
    const float* off1_w  = (const float*)d_in[9];
    const float* off2_w  = (const float*)d_in[10];
    const float* off3_w  = (const float*)d_in[11];
    const float* bn_g    = (const float*)d_in[12];
    const float* bn_b    = (const float*)d_in[13];
    const float* bn_m    = (const float*)d_in[14];
    const float* bn_v    = (const float*)d_in[15];
    const float* off4_w  = (const float*)d_in[16];
    const float* posemb  = (const float*)d_in[17];
    const float* proj_w  = (const float*)d_in[18];
    const float* proj_b  = (const float*)d_in[19];
    const float* ln2_g   = (const float*)d_in[20];
    const float* ln2_b   = (const float*)d_in[21];
    const float* mlp_w1  = (const float*)d_in[22];
    const float* mlp_b1  = (const float*)d_in[23];
    const float* mlp_w2  = (const float*)d_in[24];
    const float* mlp_b2  = (const float*)d_in[25];
    float* out = (float*)d_out;

    float *xa, *qbuf, *o1, *o2, *o3, *grid, *kpart, *vpart, *attno, *y1, *xm, *hdn;
    cudaGetSymbolAddress((void**)&xa,    g_xa);
    cudaGetSymbolAddress((void**)&qbuf,  g_q);
    cudaGetSymbolAddress((void**)&o1,    g_o1);
    cudaGetSymbolAddress((void**)&o2,    g_o2);
    cudaGetSymbolAddress((void**)&o3,    g_o3);
    cudaGetSymbolAddress((void**)&grid,  g_grid);
    cudaGetSymbolAddress((void**)&kpart, g_kpart);
    cudaGetSymbolAddress((void**)&vpart, g_vpart);
    cudaGetSymbolAddress((void**)&attno, g_attno);
    cudaGetSymbolAddress((void**)&y1,    g_y1);
    cudaGetSymbolAddress((void**)&xm,    g_xm);
    cudaGetSymbolAddress((void**)&hdn,   g_hdn);

    cudaFuncSetAttribute(attn_kernel, cudaFuncAttributeMaxDynamicSharedMemorySize, 100352);

    // 1. LN1
    ln2d_kernel<<<256, 256>>>(x, ln1_g, ln1_b, xa);

    // 2. q = q_w @ xa + q_b
    sgemm_kernel<<<dim3(64, 4, 2), 256>>>(q_w, xa, qbuf, q_b, nullptr,
        256, 4096, 256, 256, 1048576LL, 1048576LL, 0LL, 1);

    // 3. dw conv chain (q viewed as [4][128][64][64])
    dwconv_kernel<<<512, 256>>>(qbuf, off1_w, o1, 64, 32, 0, nullptr, nullptr, nullptr, nullptr);
    dwconv_kernel<<<512, 256>>>(o1, off2_w, o2, 32, 16, 0, nullptr, nullptr, nullptr, nullptr);
    dwconv_kernel<<<512, 256>>>(o2, off3_w, o3, 16, 8, 1, bn_g, bn_b, bn_m, bn_v);

    // 4. off = off4_w @ o3  (reuse o1 as [4][2048][64])
    sgemm_kernel<<<dim3(1, 32, 4), 256>>>(off4_w, o3, o1, nullptr, nullptr,
        2048, 64, 128, 128, 8192LL, 131072LL, 0LL, 0);

    // 5. sampling grid (pixel coords)
    grid_kernel<<<2048, 256>>>(o1, grid);

    // 6. kpart/vpart: per (b,g) half-projection, output transposed [pix][256]
    for (int bg = 0; bg < 4; bg++) {
        int b = bg >> 1, g = bg & 1;
        const float* Bk = xa + (size_t)b * 1048576 + (size_t)g * 524288;
        sgemm_kernel<<<dim3(64, 4, 1), 256>>>(k_w + g * 128, Bk,
            kpart + (size_t)bg * 1048576, nullptr, nullptr,
            256, 4096, 128, 256, 0LL, 0LL, 0LL, 8);
        sgemm_kernel<<<dim3(64, 4, 1), 256>>>(v_w + g * 128, Bk,
            vpart + (size_t)bg * 1048576, nullptr, nullptr,
            256, 4096, 128, 256, 0LL, 0LL, 0LL, 8);
    }

    // 7. fused sampling + attention
    attn_kernel<<<1024, 256, 97712>>>(qbuf, kpart, vpart, grid, k_b, v_b, posemb, attno);

    // 8. y1 = x + proj_w @ attno + proj_b
    sgemm_kernel<<<dim3(64, 4, 2), 256>>>(proj_w, attno, y1, proj_b, x,
        256, 4096, 256, 256, 1048576LL, 1048576LL, 1048576LL, 1 | 4);

    // 9. LN2
    ln2d_kernel<<<256, 256>>>(y1, ln2_g, ln2_b, xm);

    // 10. hdn = gelu(mlp_w1 @ xm + b1)
    sgemm_kernel<<<dim3(64, 16, 2), 256>>>(mlp_w1, xm, hdn, mlp_b1, nullptr,
        1024, 4096, 256, 256, 1048576LL, 4194304LL, 0LL, 1 | 2);

    // 11. out = y1 + mlp_w2 @ hdn + b2
    sgemm_kernel<<<dim3(64, 4, 2), 256>>>(mlp_w2, hdn, out, mlp_b2, y1,
        256, 4096, 1024, 1024, 4194304LL, 1048576LL, 1048576LL, 1 | 4);
}

// round 13
// speedup vs baseline: 1.1668x; 1.1668x over previous
#include <cuda_runtime.h>
#include <math.h>

// ---------------------------------------------------------------------------
// Constants: B=2, DIM=256, H=W=64, HEADS=8, HC=32, HG=2, GC=128,
// STRIDE=2 -> RH=RW=32, R=1024 ; WS=8 -> WH=WW=8, NW=64, WT=64 ; MLP_HID=1024
// ---------------------------------------------------------------------------

__device__ float g_xa[2097152];     // [2][256][4096]
__device__ float g_q[2097152];      // [2][256][4096]
__device__ float g_o1[524288];      // dw1 out; reused for off [4][2048][64]
__device__ float g_o2[131072];      // [4][128][16*16]
__device__ float g_o3[32768];       // [4][128][64]
__device__ float g_grid[524288];    // [4][64][1024][2]  (row_pix, col_pix)
__device__ float g_kpart[4194304];  // [4][4096][256] pixel-major
__device__ float g_vpart[4194304];
__device__ float g_attno[2097152];  // [2][256][4096]
__device__ float g_y1[2097152];
__device__ float g_xm[2097152];
__device__ float g_hdn[8388608];    // [2][1024][4096]

__device__ __forceinline__ float gelu_f(float v) {
    return 0.5f * v * (1.0f + erff(v * 0.70710678118654752440f));
}

__device__ __forceinline__ unsigned tf32_of(float f) {
    unsigned u;
    asm("cvt.rna.tf32.f32 %0, %1;" : "=r"(u) : "f"(f));
    return u;
}

// ---------------------------------------------------------------------------
// LayerNorm over 256 channels per pixel. Block = 32 pixels, 8 warps.
// ---------------------------------------------------------------------------
__global__ __launch_bounds__(256) void ln2d_kernel(
    const float* __restrict__ x, const float* __restrict__ g,
    const float* __restrict__ bt, float* __restrict__ out)
{
    int lane = threadIdx.x & 31, wz = threadIdx.x >> 5;
    int pix = blockIdx.x * 32 + lane;
    int b = pix >> 12, p = pix & 4095;
    const float* xb = x + (size_t)b * 1048576 + p;
    float v[32];
    float s = 0.f, sq = 0.f;
#pragma unroll
    for (int i = 0; i < 32; i++) {
        int c = wz + i * 8;
        float t = xb[(size_t)c * 4096];
        v[i] = t; s += t; sq += t * t;
    }
    __shared__ float ssum[8][33], ssq[8][33];
    __shared__ float smu[32], srs[32];
    ssum[wz][lane] = s; ssq[wz][lane] = sq;
    __syncthreads();
    if (wz == 0) {
        float S = 0.f, Q = 0.f;
#pragma unroll
        for (int i = 0; i < 8; i++) { S += ssum[i][lane]; Q += ssq[i][lane]; }
        float mu = S * (1.f / 256.f);
        float var = Q * (1.f / 256.f) - mu * mu;
        smu[lane] = mu;
        srs[lane] = rsqrtf(var + 1e-5f);
    }
    __syncthreads();
    float mu = smu[lane], rs = srs[lane];
    float* ob = out + (size_t)b * 1048576 + p;
#pragma unroll
    for (int i = 0; i < 32; i++) {
        int c = wz + i * 8;
        ob[(size_t)c * 4096] = (v[i] - mu) * rs * g[c] + bt[c];
    }
}

// ---------------------------------------------------------------------------
// TF32 tensor-core GEMM: C[m][n] = sum_k A[m*lda+k] * B[k*N+n]
// Tile 64x64, K-chunk 16, 256 threads (8 warps), mma.sync.m16n8k8.
// flags: 1=bias 2=gelu 4=residual 8=transpose_out
// ---------------------------------------------------------------------------
__global__ __launch_bounds__(256) void sgemm_kernel(
    const float* __restrict__ A, const float* __restrict__ B, float* __restrict__ C,
    const float* __restrict__ bias, const float* __restrict__ res,
    int M, int N, int K, int lda,
    long long strideB, long long strideC, long long strideRes, int flags)
{
    int bz = blockIdx.z;
    B += (long long)bz * strideB;
    C += (long long)bz * strideC;
    if (res) res += (long long)bz * strideRes;

    int m0 = blockIdx.y * 64, n0 = blockIdx.x * 64;
    __shared__ unsigned As[16][72];   // As[k][m]  (tf32 bits)
    __shared__ unsigned Bs[16][72];   // Bs[k][n]  (tf32 bits)
    int tid = threadIdx.x;
    int lane = tid & 31, warp = tid >> 5;
    int la_m = tid >> 4, la_k = tid & 15;
    int lb_k = tid >> 6, lb_n = tid & 63;

    int g = lane >> 2, tg = lane & 3;      // fragment coords
    int mrow = (warp & 3) * 16;
    int ncol = (warp >> 2) * 32;

    float d[4][4];
#pragma unroll
    for (int j = 0; j < 4; j++)
#pragma unroll
        for (int i = 0; i < 4; i++) d[j][i] = 0.f;

    for (int k0 = 0; k0 < K; k0 += 16) {
#pragma unroll
        for (int r = 0; r < 4; r++)
            As[la_k][la_m + 16 * r] = tf32_of(A[(size_t)(m0 + la_m + 16 * r) * lda + k0 + la_k]);
#pragma unroll
        for (int r = 0; r < 4; r++)
            Bs[lb_k + 4 * r][lb_n] = tf32_of(B[(size_t)(k0 + lb_k + 4 * r) * N + n0 + lb_n]);
        __syncthreads();

#pragma unroll
        for (int ks = 0; ks < 16; ks += 8) {
            unsigned a0 = As[ks + tg][mrow + g];
            unsigned a1 = As[ks + tg][mrow + g + 8];
            unsigned a2 = As[ks + tg + 4][mrow + g];
            unsigned a3 = As[ks + tg + 4][mrow + g + 8];
#pragma unroll
            for (int j = 0; j < 4; j++) {
                unsigned b0 = Bs[ks + tg][ncol + 8 * j + g];
                unsigned b1 = Bs[ks + tg + 4][ncol + 8 * j + g];
                asm volatile(
                    "mma.sync.aligned.m16n8k8.row.col.f32.tf32.tf32.f32 "
                    "{%0,%1,%2,%3}, {%4,%5,%6,%7}, {%8,%9}, {%0,%1,%2,%3};\n"
                    : "+f"(d[j][0]), "+f"(d[j][1]), "+f"(d[j][2]), "+f"(d[j][3])
                    : "r"(a0), "r"(a1), "r"(a2), "r"(a3), "r"(b0), "r"(b1));
            }
        }
        __syncthreads();
    }

#pragma unroll
    for (int half = 0; half < 2; half++) {
        int m = m0 + mrow + g + half * 8;
        float bv = (flags & 1) ? bias[m] : 0.f;
#pragma unroll
        for (int j = 0; j < 4; j++) {
#pragma unroll
            for (int e = 0; e < 2; e++) {
                int n = n0 + ncol + 8 * j + 2 * tg + e;
                float v = d[j][half * 2 + e] + bv;
                if (flags & 2) v = gelu_f(v);
                if (flags & 4) v += res[(size_t)m * N + n];
                if (flags & 8) C[(size_t)n * M + m] = v;
                else           C[(size_t)m * N + n] = v;
            }
        }
    }
}

// ---------------------------------------------------------------------------
// Depthwise 3x3 stride-2 pad-1 conv; optional BN + exact GELU.
// ---------------------------------------------------------------------------
__global__ __launch_bounds__(256) void dwconv_kernel(
    const float* __restrict__ in, const float* __restrict__ w9, float* __restrict__ out,
    int Hi, int Ho, int do_bn,
    const float* __restrict__ bn_g, const float* __restrict__ bn_b,
    const float* __restrict__ bn_m, const float* __restrict__ bn_v)
{
    int bc = blockIdx.x;
    int c = bc & 127;
    const float* ip = in + (size_t)bc * Hi * Hi;
    float* op = out + (size_t)bc * Ho * Ho;
    float wv[9];
#pragma unroll
    for (int i = 0; i < 9; i++) wv[i] = w9[c * 9 + i];
    float bg = 0.f, bb = 0.f, bm = 0.f, brs = 1.f;
    if (do_bn) {
        bg = bn_g[c]; bb = bn_b[c]; bm = bn_m[c];
        brs = rsqrtf(bn_v[c] + 1e-5f);
    }
    for (int idx = threadIdx.x; idx < Ho * Ho; idx += blockDim.x) {
        int oy = idx / Ho, ox = idx - oy * Ho;
        int iy0 = oy * 2 - 1, ix0 = ox * 2 - 1;
        float s = 0.f;
#pragma unroll
        for (int ki = 0; ki < 3; ki++) {
            int iy = iy0 + ki;
            if (iy < 0 || iy >= Hi) continue;
#pragma unroll
            for (int kj = 0; kj < 3; kj++) {
                int ix = ix0 + kj;
                if (ix < 0 || ix >= Hi) continue;
                s += ip[iy * Hi + ix] * wv[ki * 3 + kj];
            }
        }
        if (do_bn) {
            s = (s - bm) * brs * bg + bb;
            s = gelu_f(s);
        }
        op[idx] = s;
    }
}

// ---------------------------------------------------------------------------
// Build sampling grid in PIXEL coords. off: [4][2048][64], grid: [4][64][1024][2]
// ---------------------------------------------------------------------------
__global__ __launch_bounds__(256) void grid_kernel(
    const float* __restrict__ off, float* __restrict__ grid)
{
    int idx = blockIdx.x * 256 + threadIdx.x;       // 0 .. 524287
    int d = idx & 1;
    int r = (idx >> 1) & 1023;
    int w = (idx >> 11) & 63;
    int bg = idx >> 17;
    float v = tanhf(off[((size_t)bg * 2048 + d * 1024 + r) * 64 + w]);
    int i = d ? (r & 31) : (r >> 5);
    float ref = 4.0f * (float)i / 63.0f - 1.0f;
    grid[idx] = (v * 0.03125f + ref + 1.0f) * 31.5f;
}

// ---------------------------------------------------------------------------
// Fused sampling + windowed deformable attention (flash-style, fp32 SIMT).
// Block per (b, head, w): 256 threads = 8 warps, warp owns 8 queries.
// Gather is warp-per-row, lane-per-channel (coalesced 128B per tap):
// warps 0-3 gather K rows, warps 4-7 gather V rows (32 rows each per tile).
// ---------------------------------------------------------------------------
__global__ __launch_bounds__(256) void attn_kernel(
    const float* __restrict__ q,
    const float* __restrict__ kpart, const float* __restrict__ vpart,
    const float* __restrict__ grid,
    const float* __restrict__ k_b, const float* __restrict__ v_b,
    const float* __restrict__ posembed,
    float* __restrict__ attno)
{
    int blk = blockIdx.x;
    int w = blk & 63, head = (blk >> 6) & 7, b = blk >> 9;
    int wh = w >> 3, ww = w & 7;
    int tid = threadIdx.x;
    int lane = tid & 31, warp = tid >> 5;
    int cbase = head * 32;

    extern __shared__ float sm[];
    float* Qs  = sm;                 // [64][33]   = 2112
    float* pes = Qs + 2112;          // [70][71]   = 4970, padded to 4972
    float* Ks  = pes + 4972;         // [32][132]  = 4224
    float* Vs  = Ks + 4224;          // [128][36]  = 4608
    float* Ss  = Vs + 4608;          // [64][132]  = 8448
    float* bias_s = Ss + 8448;       // [64]  (K bias 0..31, V bias 32..63)
    // total 24428 floats = 97712 bytes

    // Load Q (scaled by C^-0.5 = 1/16)
    {
        const float* qb = q + (size_t)b * 1048576 + (size_t)cbase * 4096;
        int c = tid >> 3, t0 = tid & 7;
#pragma unroll
        for (int tr = 0; tr < 8; tr++) {
            int t = tr * 8 + t0;
            int pix = (wh * 8 + tr) * 64 + ww * 8 + t0;
            Qs[t * 33 + c] = qb[(size_t)c * 4096 + pix] * 0.0625f;
        }
    }
    // Biases for this head slice
    if (tid < 32) bias_s[tid] = k_b[cbase + tid];
    else if (tid < 64) bias_s[tid] = v_b[cbase + tid - 32];
    // Load posembed patch: rows [56-8wh, +70), cols [56-8ww, +70)
    {
        int row0 = 56 - wh * 8, col0 = 56 - ww * 8;
        const float* pe = posembed + (size_t)head * 16129;
        for (int idx = tid; idx < 4900; idx += 256) {
            int i = idx / 70, j = idx - i * 70;
            pes[i * 71 + j] = pe[(row0 + i) * 127 + col0 + j];
        }
    }

    float m_i[8], l_i[8], o_acc[8];
#pragma unroll
    for (int i = 0; i < 8; i++) { m_i[i] = -1e30f; l_i[i] = 0.f; o_acc[i] = 0.f; }
    int qbase = warp * 8;

    // Per-block grid base pointers (both groups of this batch)
    const float* gp0 = grid + (((size_t)(b * 2 + 0) * 64 + w) * 1024) * 2;
    const float* gp1 = grid + (((size_t)(b * 2 + 1) * 64 + w) * 1024) * 2;
    const float* kp0 = kpart + (size_t)(b * 2 + 0) * 1048576 + cbase;
    const float* kp1 = kpart + (size_t)(b * 2 + 1) * 1048576 + cbase;
    const float* vp0 = vpart + (size_t)(b * 2 + 0) * 1048576 + cbase;
    const float* vp1 = vpart + (size_t)(b * 2 + 1) * 1048576 + cbase;

    for (int rt = 0; rt < 1024; rt += 128) {
        __syncthreads();
        // Gather: task t = warp*32+i ; warps 0-3 -> K rows, warps 4-7 -> V rows.
        // Lane = channel: each tap is one coalesced 128B sector per warp.
        {
            int tensor = warp >> 2;                       // 0 = K, 1 = V
            const float* s0 = tensor ? vp0 : kp0;
            const float* s1 = tensor ? vp1 : kp1;
            float bv = bias_s[tensor * 32 + lane];
#pragma unroll 4
            for (int i = 0; i < 32; i++) {
                int r = (warp & 3) * 32 + i;              // 0..127
                int rg = rt + r;
                float acc = bv;
#pragma unroll
                for (int g2 = 0; g2 < 2; g2++) {
                    const float* gp = (g2 ? gp1 : gp0) + rg * 2;
                    const float* src = g2 ? s1 : s0;
                    float row = gp[0], col = gp[1];
                    float r0f = floorf(row), c0f = floorf(col);
                    float wr = row - r0f, wc = col - c0f;
                    int r0 = (int)r0f, c0 = (int)c0f;
#pragma unroll
                    for (int t = 0; t < 4; t++) {
                        int ri = r0 + (t >> 1), ci = c0 + (t & 1);
                        float wt = ((t >> 1) ? wr : 1.0f - wr) * ((t & 1) ? wc : 1.0f - wc);
                        if (ri >= 0 && ri < 64 && ci >= 0 && ci < 64)
                            acc += wt * __ldg(src + (size_t)(ri * 64 + ci) * 256 + lane);
                    }
                }
                if (tensor == 0) Ks[lane * 132 + r] = acc;
                else             Vs[r * 36 + lane] = acc;
            }
        }
        __syncthreads();

        // S = Q K^T : thread owns (qbase+i, lane+32j)
        float s[8][4];
#pragma unroll
        for (int i = 0; i < 8; i++)
#pragma unroll
            for (int j = 0; j < 4; j++) s[i][j] = 0.f;
#pragma unroll 4
        for (int c = 0; c < 32; c++) {
            float kv[4];
#pragma unroll
            for (int j = 0; j < 4; j++) kv[j] = Ks[c * 132 + lane + 32 * j];
#pragma unroll
            for (int i = 0; i < 8; i++) {
                float qv = Qs[(qbase + i) * 33 + c];
#pragma unroll
                for (int j = 0; j < 4; j++) s[i][j] += qv * kv[j];
            }
        }
        // + relative position bias from pe patch
#pragma unroll
        for (int i = 0; i < 8; i++) {
            int qq = qbase + i; int tr = qq >> 3, tc = qq & 7;
#pragma unroll
            for (int j = 0; j < 4; j++) {
                int r = rt + lane + 32 * j;
                int ry = r >> 5, rx = r & 31;
                s[i][j] += pes[(2 * ry - tr + 7) * 71 + (2 * rx - tc + 7)];
            }
        }
        // Online softmax per query
#pragma unroll
        for (int i = 0; i < 8; i++) {
            float mx = s[i][0];
#pragma unroll
            for (int j = 1; j < 4; j++) mx = fmaxf(mx, s[i][j]);
#pragma unroll
            for (int off = 16; off > 0; off >>= 1)
                mx = fmaxf(mx, __shfl_xor_sync(0xffffffffu, mx, off));
            float mnew = fmaxf(m_i[i], mx);
            float corr = __expf(m_i[i] - mnew);
            m_i[i] = mnew;
            float psum = 0.f;
            float p4[4];
#pragma unroll
            for (int j = 0; j < 4; j++) {
                p4[j] = __expf(s[i][j] - mnew);
                psum += p4[j];
            }
#pragma unroll
            for (int off = 16; off > 0; off >>= 1)
                psum += __shfl_xor_sync(0xffffffffu, psum, off);
            l_i[i] = l_i[i] * corr + psum;
            o_acc[i] *= corr;
#pragma unroll
            for (int j = 0; j < 4; j++)
                Ss[(qbase + i) * 132 + lane + 32 * j] = p4[j];
        }
        __syncwarp();
        // O += P V : thread owns column c=lane for queries qbase..qbase+7
#pragma unroll 2
        for (int rl = 0; rl < 128; rl++) {
            float v = Vs[rl * 36 + lane];
#pragma unroll
            for (int i = 0; i < 8; i++)
                o_acc[i] += Ss[(qbase + i) * 132 + rl] * v;
        }
        __syncwarp();
    }

    // Write attno[b][cbase+lane][pix]
    float* ao = attno + (size_t)b * 1048576 + (size_t)(cbase + lane) * 4096;
#pragma unroll
    for (int i = 0; i < 8; i++) {
        int qq = qbase + i; int tr = qq >> 3, tc = qq & 7;
        int pix = (wh * 8 + tr) * 64 + ww * 8 + tc;
        ao[pix] = o_acc[i] / l_i[i];
    }
}

// ---------------------------------------------------------------------------
// Host launcher
// ---------------------------------------------------------------------------
extern "C" void kernel_launch(void* const* d_in, const int* in_sizes, int n_in,
                              void* d_out, int out_size)
{
    const float* x       = (const float*)d_in[0];
    const float* ln1_g   = (const float*)d_in[1];
    const float* ln1_b   = (const float*)d_in[2];
    const float* q_w     = (const float*)d_in[3];
    const float* q_b     = (const float*)d_in[4];
    const float* k_w     = (const float*)d_in[5];
    const float* k_b     = (const float*)d_in[6];
    const float* v_w     = (const float*)d_in[7];
    const float* v_b     = (const float*)d_in[8];
    const float* off1_w  = (const float*)d_in[9];
    const float* off2_w  = (const float*)d_in[10];
    const float* off3_w  = (const float*)d_in[11];
    const float* bn_g    = (const float*)d_in[12];
    const float* bn_b    = (const float*)d_in[13];
    const float* bn_m    = (const float*)d_in[14];
    const float* bn_v    = (const float*)d_in[15];
    const float* off4_w  = (const float*)d_in[16];
    const float* posemb  = (const float*)d_in[17];
    const float* proj_w  = (const float*)d_in[18];
    const float* proj_b  = (const float*)d_in[19];
    const float* ln2_g   = (const float*)d_in[20];
    const float* ln2_b   = (const float*)d_in[21];
    const float* mlp_w1  = (const float*)d_in[22];
    const float* mlp_b1  = (const float*)d_in[23];
    const float* mlp_w2  = (const float*)d_in[24];
    const float* mlp_b2  = (const float*)d_in[25];
    float* out = (float*)d_out;

    float *xa, *qbuf, *o1, *o2, *o3, *grid, *kpart, *vpart, *attno, *y1, *xm, *hdn;
    cudaGetSymbolAddress((void**)&xa,    g_xa);
    cudaGetSymbolAddress((void**)&qbuf,  g_q);
    cudaGetSymbolAddress((void**)&o1,    g_o1);
    cudaGetSymbolAddress((void**)&o2,    g_o2);
    cudaGetSymbolAddress((void**)&o3,    g_o3);
    cudaGetSymbolAddress((void**)&grid,  g_grid);
    cudaGetSymbolAddress((void**)&kpart, g_kpart);
    cudaGetSymbolAddress((void**)&vpart, g_vpart);
    cudaGetSymbolAddress((void**)&attno, g_attno);
    cudaGetSymbolAddress((void**)&y1,    g_y1);
    cudaGetSymbolAddress((void**)&xm,    g_xm);
    cudaGetSymbolAddress((void**)&hdn,   g_hdn);

    cudaFuncSetAttribute(attn_kernel, cudaFuncAttributeMaxDynamicSharedMemorySize, 100352);

    // 1. LN1
    ln2d_kernel<<<256, 256>>>(x, ln1_g, ln1_b, xa);

    // 2. q = q_w @ xa + q_b
    sgemm_kernel<<<dim3(64, 4, 2), 256>>>(q_w, xa, qbuf, q_b, nullptr,
        256, 4096, 256, 256, 1048576LL, 1048576LL, 0LL, 1);

    // 3. dw conv chain (q viewed as [4][128][64][64])
    dwconv_kernel<<<512, 256>>>(qbuf, off1_w, o1, 64, 32, 0, nullptr, nullptr, nullptr, nullptr);
    dwconv_kernel<<<512, 256>>>(o1, off2_w, o2, 32, 16, 0, nullptr, nullptr, nullptr, nullptr);
    dwconv_kernel<<<512, 256>>>(o2, off3_w, o3, 16, 8, 1, bn_g, bn_b, bn_m, bn_v);

    // 4. off = off4_w @ o3  (reuse o1 as [4][2048][64])
    sgemm_kernel<<<dim3(1, 32, 4), 256>>>(off4_w, o3, o1, nullptr, nullptr,
        2048, 64, 128, 128, 8192LL, 131072LL, 0LL, 0);

    // 5. sampling grid (pixel coords)
    grid_kernel<<<2048, 256>>>(o1, grid);

    // 6. kpart/vpart: per (b,g) half-projection, output transposed [pix][256]
    for (int bg = 0; bg < 4; bg++) {
        int b = bg >> 1, g = bg & 1;
        const float* Bk = xa + (size_t)b * 1048576 + (size_t)g * 524288;
        sgemm_kernel<<<dim3(64, 4, 1), 256>>>(k_w + g * 128, Bk,
            kpart + (size_t)bg * 1048576, nullptr, nullptr,
            256, 4096, 128, 256, 0LL, 0LL, 0LL, 8);
        sgemm_kernel<<<dim3(64, 4, 1), 256>>>(v_w + g * 128, Bk,
            vpart + (size_t)bg * 1048576, nullptr, nullptr,
            256, 4096, 128, 256, 0LL, 0LL, 0LL, 8);
    }

    // 7. fused sampling + attention
    attn_kernel<<<1024, 256, 97712>>>(qbuf, kpart, vpart, grid, k_b, v_b, posemb, attno);

    // 8. y1 = x + proj_w @ attno + proj_b
    sgemm_kernel<<<dim3(64, 4, 2), 256>>>(proj_w, attno, y1, proj_b, x,
        256, 4096, 256, 256, 1048576LL, 1048576LL, 1048576LL, 1 | 4);

    // 9. LN2
    ln2d_kernel<<<256, 256>>>(y1, ln2_g, ln2_b, xm);

    // 10. hdn = gelu(mlp_w1 @ xm + b1)
    sgemm_kernel<<<dim3(64, 16, 2), 256>>>(mlp_w1, xm, hdn, mlp_b1, nullptr,
        1024, 4096, 256, 256, 1048576LL, 4194304LL, 0LL, 1 | 2);

    // 11. out = y1 + mlp_w2 @ hdn + b2
    sgemm_kernel<<<dim3(64, 4, 2), 256>>>(mlp_w2, hdn, out, mlp_b2, y1,
        256, 4096, 1024, 1024, 4194304LL, 1048576LL, 1048576LL, 1 | 4);
}

// round 17
// speedup vs baseline: 1.3423x; 1.1504x over previous
#include <cuda_runtime.h>
#include <math.h>

// ---------------------------------------------------------------------------
// Constants: B=2, DIM=256, H=W=64, HEADS=8, HC=32, HG=2, GC=128,
// STRIDE=2 -> RH=RW=32, R=1024 ; WS=8 -> WH=WW=8, NW=64, WT=64 ; MLP_HID=1024
// ---------------------------------------------------------------------------

__device__ float g_xa[2097152];     // [2][256][4096]
__device__ float g_q[2097152];      // [2][256][4096]
__device__ float g_o1[524288];      // dw1 out; reused for off [4][2048][64]
__device__ float g_o2[131072];      // [4][128][16*16]
__device__ float g_o3[32768];       // [4][128][64]
__device__ float g_grid[524288];    // [4][64][1024][2]  (row_pix, col_pix)
__device__ float g_kpart[4194304];  // [4][4096][256] pixel-major
__device__ float g_vpart[4194304];
__device__ float g_kk[33554432];    // [2][64][1024][256]
__device__ float g_vv[33554432];
__device__ float g_attno[2097152];  // [2][256][4096]
__device__ float g_y1[2097152];
__device__ float g_xm[2097152];
__device__ float g_hdn[8388608];    // [2][1024][4096]

__device__ __forceinline__ float gelu_f(float v) {
    return 0.5f * v * (1.0f + erff(v * 0.70710678118654752440f));
}

__device__ __forceinline__ unsigned tf32_of(float f) {
    unsigned u;
    asm("cvt.rna.tf32.f32 %0, %1;" : "=r"(u) : "f"(f));
    return u;
}

// ---------------------------------------------------------------------------
// LayerNorm over 256 channels per pixel. Block = 32 pixels, 8 warps.
// ---------------------------------------------------------------------------
__global__ __launch_bounds__(256) void ln2d_kernel(
    const float* __restrict__ x, const float* __restrict__ g,
    const float* __restrict__ bt, float* __restrict__ out)
{
    int lane = threadIdx.x & 31, wz = threadIdx.x >> 5;
    int pix = blockIdx.x * 32 + lane;
    int b = pix >> 12, p = pix & 4095;
    const float* xb = x + (size_t)b * 1048576 + p;
    float v[32];
    float s = 0.f, sq = 0.f;
#pragma unroll
    for (int i = 0; i < 32; i++) {
        int c = wz + i * 8;
        float t = xb[(size_t)c * 4096];
        v[i] = t; s += t; sq += t * t;
    }
    __shared__ float ssum[8][33], ssq[8][33];
    __shared__ float smu[32], srs[32];
    ssum[wz][lane] = s; ssq[wz][lane] = sq;
    __syncthreads();
    if (wz == 0) {
        float S = 0.f, Q = 0.f;
#pragma unroll
        for (int i = 0; i < 8; i++) { S += ssum[i][lane]; Q += ssq[i][lane]; }
        float mu = S * (1.f / 256.f);
        float var = Q * (1.f / 256.f) - mu * mu;
        smu[lane] = mu;
        srs[lane] = rsqrtf(var + 1e-5f);
    }
    __syncthreads();
    float mu = smu[lane], rs = srs[lane];
    float* ob = out + (size_t)b * 1048576 + p;
#pragma unroll
    for (int i = 0; i < 32; i++) {
        int c = wz + i * 8;
        ob[(size_t)c * 4096] = (v[i] - mu) * rs * g[c] + bt[c];
    }
}

// ---------------------------------------------------------------------------
// TF32 tensor-core GEMM: C[m][n] = sum_k A[m*lda+k] * B[k*N+n]
// Tile 64x64, K-chunk 16, 256 threads (8 warps), mma.sync.m16n8k8.
// flags: 1=bias 2=gelu 4=residual 8=transpose_out
// ---------------------------------------------------------------------------
__global__ __launch_bounds__(256) void sgemm_kernel(
    const float* __restrict__ A, const float* __restrict__ B, float* __restrict__ C,
    const float* __restrict__ bias, const float* __restrict__ res,
    int M, int N, int K, int lda,
    long long strideB, long long strideC, long long strideRes, int flags)
{
    int bz = blockIdx.z;
    B += (long long)bz * strideB;
    C += (long long)bz * strideC;
    if (res) res += (long long)bz * strideRes;

    int m0 = blockIdx.y * 64, n0 = blockIdx.x * 64;
    __shared__ unsigned As[16][72];   // As[k][m]  (tf32 bits)
    __shared__ unsigned Bs[16][72];   // Bs[k][n]  (tf32 bits)
    int tid = threadIdx.x;
    int lane = tid & 31, warp = tid >> 5;
    int la_m = tid >> 4, la_k = tid & 15;
    int lb_k = tid >> 6, lb_n = tid & 63;

    int g = lane >> 2, tg = lane & 3;      // fragment coords
    int mrow = (warp & 3) * 16;
    int ncol = (warp >> 2) * 32;

    float d[4][4];
#pragma unroll
    for (int j = 0; j < 4; j++)
#pragma unroll
        for (int i = 0; i < 4; i++) d[j][i] = 0.f;

    for (int k0 = 0; k0 < K; k0 += 16) {
#pragma unroll
        for (int r = 0; r < 4; r++)
            As[la_k][la_m + 16 * r] = tf32_of(A[(size_t)(m0 + la_m + 16 * r) * lda + k0 + la_k]);
#pragma unroll
        for (int r = 0; r < 4; r++)
            Bs[lb_k + 4 * r][lb_n] = tf32_of(B[(size_t)(k0 + lb_k + 4 * r) * N + n0 + lb_n]);
        __syncthreads();

#pragma unroll
        for (int ks = 0; ks < 16; ks += 8) {
            unsigned a0 = As[ks + tg][mrow + g];
            unsigned a1 = As[ks + tg][mrow + g + 8];
            unsigned a2 = As[ks + tg + 4][mrow + g];
            unsigned a3 = As[ks + tg + 4][mrow + g + 8];
#pragma unroll
            for (int j = 0; j < 4; j++) {
                unsigned b0 = Bs[ks + tg][ncol + 8 * j + g];
                unsigned b1 = Bs[ks + tg + 4][ncol + 8 * j + g];
                asm volatile(
                    "mma.sync.aligned.m16n8k8.row.col.f32.tf32.tf32.f32 "
                    "{%0,%1,%2,%3}, {%4,%5,%6,%7}, {%8,%9}, {%0,%1,%2,%3};\n"
                    : "+f"(d[j][0]), "+f"(d[j][1]), "+f"(d[j][2]), "+f"(d[j][3])
                    : "r"(a0), "r"(a1), "r"(a2), "r"(a3), "r"(b0), "r"(b1));
            }
        }
        __syncthreads();
    }

#pragma unroll
    for (int half = 0; half < 2; half++) {
        int m = m0 + mrow + g + half * 8;
        float bv = (flags & 1) ? bias[m] : 0.f;
#pragma unroll
        for (int j = 0; j < 4; j++) {
#pragma unroll
            for (int e = 0; e < 2; e++) {
                int n = n0 + ncol + 8 * j + 2 * tg + e;
                float v = d[j][half * 2 + e] + bv;
                if (flags & 2) v = gelu_f(v);
                if (flags & 4) v += res[(size_t)m * N + n];
                if (flags & 8) C[(size_t)n * M + m] = v;
                else           C[(size_t)m * N + n] = v;
            }
        }
    }
}

// ---------------------------------------------------------------------------
// Depthwise 3x3 stride-2 pad-1 conv; optional BN + exact GELU.
// ---------------------------------------------------------------------------
__global__ __launch_bounds__(256) void dwconv_kernel(
    const float* __restrict__ in, const float* __restrict__ w9, float* __restrict__ out,
    int Hi, int Ho, int do_bn,
    const float* __restrict__ bn_g, const float* __restrict__ bn_b,
    const float* __restrict__ bn_m, const float* __restrict__ bn_v)
{
    int bc = blockIdx.x;
    int c = bc & 127;
    const float* ip = in + (size_t)bc * Hi * Hi;
    float* op = out + (size_t)bc * Ho * Ho;
    float wv[9];
#pragma unroll
    for (int i = 0; i < 9; i++) wv[i] = w9[c * 9 + i];
    float bg = 0.f, bb = 0.f, bm = 0.f, brs = 1.f;
    if (do_bn) {
        bg = bn_g[c]; bb = bn_b[c]; bm = bn_m[c];
        brs = rsqrtf(bn_v[c] + 1e-5f);
    }
    for (int idx = threadIdx.x; idx < Ho * Ho; idx += blockDim.x) {
        int oy = idx / Ho, ox = idx - oy * Ho;
        int iy0 = oy * 2 - 1, ix0 = ox * 2 - 1;
        float s = 0.f;
#pragma unroll
        for (int ki = 0; ki < 3; ki++) {
            int iy = iy0 + ki;
            if (iy < 0 || iy >= Hi) continue;
#pragma unroll
            for (int kj = 0; kj < 3; kj++) {
                int ix = ix0 + kj;
                if (ix < 0 || ix >= Hi) continue;
                s += ip[iy * Hi + ix] * wv[ki * 3 + kj];
            }
        }
        if (do_bn) {
            s = (s - bm) * brs * bg + bb;
            s = gelu_f(s);
        }
        op[idx] = s;
    }
}

// ---------------------------------------------------------------------------
// Build sampling grid in PIXEL coords. off: [4][2048][64], grid: [4][64][1024][2]
// ---------------------------------------------------------------------------
__global__ __launch_bounds__(256) void grid_kernel(
    const float* __restrict__ off, float* __restrict__ grid)
{
    int idx = blockIdx.x * 256 + threadIdx.x;       // 0 .. 524287
    int d = idx & 1;
    int r = (idx >> 1) & 1023;
    int w = (idx >> 11) & 63;
    int bg = idx >> 17;
    float v = tanhf(off[((size_t)bg * 2048 + d * 1024 + r) * 64 + w]);
    int i = d ? (r & 31) : (r >> 5);
    float ref = 4.0f * (float)i / 63.0f - 1.0f;
    grid[idx] = (v * 0.03125f + ref + 1.0f) * 31.5f;
}

// ---------------------------------------------------------------------------
// Bilinear sample kpart/vpart -> kk/vv (point-major, +bias always).
// Block = (b, w, rchunk of 8), 256 threads = channels.
// ---------------------------------------------------------------------------
__global__ __launch_bounds__(256) void sample_kernel(
    const float* __restrict__ kpart, const float* __restrict__ vpart,
    const float* __restrict__ grid,
    const float* __restrict__ k_b, const float* __restrict__ v_b,
    float* __restrict__ kk, float* __restrict__ vv)
{
    int bid = blockIdx.x;
    int rc = bid & 127, w = (bid >> 7) & 63, b = bid >> 13;
    int o = threadIdx.x;
    float kbv = k_b[o], vbv = v_b[o];
    for (int rr = 0; rr < 8; rr++) {
        int r = rc * 8 + rr;
        float ak = kbv, av = vbv;
#pragma unroll
        for (int g = 0; g < 2; g++) {
            int bg = b * 2 + g;
            const float* gp = grid + (((size_t)bg * 64 + w) * 1024 + r) * 2;
            float row = gp[0], col = gp[1];
            float r0f = floorf(row), c0f = floorf(col);
            float wr = row - r0f, wc = col - c0f;
            int r0 = (int)r0f, c0 = (int)c0f;
            const float* kp = kpart + (size_t)bg * 1048576;
            const float* vp = vpart + (size_t)bg * 1048576;
#pragma unroll
            for (int t = 0; t < 4; t++) {
                int ri = r0 + (t >> 1), ci = c0 + (t & 1);
                float wt = ((t >> 1) ? wr : 1.0f - wr) * ((t & 1) ? wc : 1.0f - wc);
                if (ri >= 0 && ri < 64 && ci >= 0 && ci < 64) {
                    size_t p = (size_t)(ri * 64 + ci) * 256 + o;
                    ak += wt * kp[p];
                    av += wt * vp[p];
                }
            }
        }
        size_t oi = (((size_t)b * 64 + w) * 1024 + r) * 256 + o;
        kk[oi] = ak;
        vv[oi] = av;
    }
}

// ---------------------------------------------------------------------------
// Fused windowed deformable attention (flash-style, fp32 SIMT, vectorized LDS).
// Block per (b, head, w): 256 threads = 8 warps, warp owns 8 queries.
// Thread owns r = lane*4 + j (4 consecutive) -> all smem traffic is float4.
// ---------------------------------------------------------------------------
__global__ __launch_bounds__(256) void attn_kernel(
    const float* __restrict__ q, const float* __restrict__ kk,
    const float* __restrict__ vv, const float* __restrict__ posembed,
    float* __restrict__ attno)
{
    int blk = blockIdx.x;
    int w = blk & 63, head = (blk >> 6) & 7, b = blk >> 9;
    int wh = w >> 3, ww = w & 7;
    int tid = threadIdx.x;
    int lane = tid & 31, warp = tid >> 5;

    extern __shared__ float sm[];
    float* Qs  = sm;                 // [64][36]   = 2304 (stride 36 -> float4-aligned chunks)
    float* pes = Qs + 2304;          // [70][71]   = 4970, padded to 4972
    float* Ks  = pes + 4972;         // [32][132]  = 4224  (base 7276, mult of 4)
    float* Vs  = Ks + 4224;          // [128][36]  = 4608  (base 11500, mult of 4 -> 16B aligned)
    float* Ss  = Vs + 4608;          // [64][132]  = 8448  (base 16108, mult of 4)
    // total 24556 floats = 98224 bytes

    // Load Q (scaled by 1/16)
    {
        const float* qb = q + (size_t)b * 1048576 + (size_t)(head * 32) * 4096;
        int c = tid >> 3, t0 = tid & 7;
#pragma unroll
        for (int tr = 0; tr < 8; tr++) {
            int t = tr * 8 + t0;
            int pix = (wh * 8 + tr) * 64 + ww * 8 + t0;
            Qs[t * 36 + c] = qb[(size_t)c * 4096 + pix] * 0.0625f;
        }
    }
    // Load posembed patch: rows [56-8wh, +70), cols [56-8ww, +70)
    {
        int row0 = 56 - wh * 8, col0 = 56 - ww * 8;
        const float* pe = posembed + (size_t)head * 16129;
        for (int idx = tid; idx < 4900; idx += 256) {
            int i = idx / 70, j = idx - i * 70;
            pes[i * 71 + j] = pe[(row0 + i) * 127 + col0 + j];
        }
    }

    float m_i[8], l_i[8], o_acc[8];
#pragma unroll
    for (int i = 0; i < 8; i++) { m_i[i] = -1e30f; l_i[i] = 0.f; o_acc[i] = 0.f; }
    int qbase = warp * 8;

    const float* kkb = kk + (((size_t)b * 64 + w) * 1024) * 256 + head * 32;
    const float* vvb = vv + (((size_t)b * 64 + w) * 1024) * 256 + head * 32;

    for (int rt = 0; rt < 1024; rt += 128) {
        __syncthreads();
        // Load K tile [32c][128r] and V tile [128r][32c]
        {
            int r = tid & 127, cb = (tid >> 7) * 16;
            const float* kr = kkb + (size_t)(rt + r) * 256 + cb;
            const float* vr = vvb + (size_t)(rt + r) * 256 + cb;
#pragma unroll
            for (int c4 = 0; c4 < 16; c4 += 4) {
                float4 kv = *(const float4*)(kr + c4);
                Ks[(cb + c4 + 0) * 132 + r] = kv.x;
                Ks[(cb + c4 + 1) * 132 + r] = kv.y;
                Ks[(cb + c4 + 2) * 132 + r] = kv.z;
                Ks[(cb + c4 + 3) * 132 + r] = kv.w;
                *(float4*)(Vs + r * 36 + cb + c4) = *(const float4*)(vr + c4);
            }
        }
        __syncthreads();

        // S = Q K^T : thread owns (qbase+i, lane*4+j), j=0..3 (consecutive r)
        float s[8][4];
#pragma unroll
        for (int i = 0; i < 8; i++)
#pragma unroll
            for (int j = 0; j < 4; j++) s[i][j] = 0.f;
#pragma unroll
        for (int c4 = 0; c4 < 32; c4 += 4) {
            float4 k0 = *(const float4*)(&Ks[(c4 + 0) * 132 + lane * 4]);
            float4 k1 = *(const float4*)(&Ks[(c4 + 1) * 132 + lane * 4]);
            float4 k2 = *(const float4*)(&Ks[(c4 + 2) * 132 + lane * 4]);
            float4 k3 = *(const float4*)(&Ks[(c4 + 3) * 132 + lane * 4]);
#pragma unroll
            for (int i = 0; i < 8; i++) {
                float4 q4 = *(const float4*)(&Qs[(qbase + i) * 36 + c4]);
                s[i][0] += q4.x * k0.x + q4.y * k1.x + q4.z * k2.x + q4.w * k3.x;
                s[i][1] += q4.x * k0.y + q4.y * k1.y + q4.z * k2.y + q4.w * k3.y;
                s[i][2] += q4.x * k0.z + q4.y * k1.z + q4.z * k2.z + q4.w * k3.z;
                s[i][3] += q4.x * k0.w + q4.y * k1.w + q4.z * k2.w + q4.w * k3.w;
            }
        }
        // + relative position bias from pe patch (r = rt + lane*4 + j)
#pragma unroll
        for (int i = 0; i < 8; i++) {
            int qq = qbase + i; int tr = qq >> 3, tc = qq & 7;
#pragma unroll
            for (int j = 0; j < 4; j++) {
                int r = rt + lane * 4 + j;
                int ry = r >> 5, rx = r & 31;
                s[i][j] += pes[(2 * ry - tr + 7) * 71 + (2 * rx - tc + 7)];
            }
        }
        // Online softmax per query (warp covers all 128 r)
#pragma unroll
        for (int i = 0; i < 8; i++) {
            float mx = s[i][0];
#pragma unroll
            for (int j = 1; j < 4; j++) mx = fmaxf(mx, s[i][j]);
#pragma unroll
            for (int off = 16; off > 0; off >>= 1)
                mx = fmaxf(mx, __shfl_xor_sync(0xffffffffu, mx, off));
            float mnew = fmaxf(m_i[i], mx);
            float corr = __expf(m_i[i] - mnew);
            m_i[i] = mnew;
            float psum = 0.f;
            float4 p4;
            p4.x = __expf(s[i][0] - mnew);
            p4.y = __expf(s[i][1] - mnew);
            p4.z = __expf(s[i][2] - mnew);
            p4.w = __expf(s[i][3] - mnew);
            psum = p4.x + p4.y + p4.z + p4.w;
#pragma unroll
            for (int off = 16; off > 0; off >>= 1)
                psum += __shfl_xor_sync(0xffffffffu, psum, off);
            l_i[i] = l_i[i] * corr + psum;
            o_acc[i] *= corr;
            *(float4*)(&Ss[(qbase + i) * 132 + lane * 4]) = p4;
        }
        __syncwarp();
        // O += P V : thread owns column c=lane for queries qbase..qbase+7
#pragma unroll 4
        for (int rl = 0; rl < 128; rl += 4) {
            float v0 = Vs[(rl + 0) * 36 + lane];
            float v1 = Vs[(rl + 1) * 36 + lane];
            float v2 = Vs[(rl + 2) * 36 + lane];
            float v3 = Vs[(rl + 3) * 36 + lane];
#pragma unroll
            for (int i = 0; i < 8; i++) {
                float4 s4 = *(const float4*)(&Ss[(qbase + i) * 132 + rl]);
                o_acc[i] += s4.x * v0 + s4.y * v1 + s4.z * v2 + s4.w * v3;
            }
        }
        __syncwarp();
    }

    // Write attno[b][head*32+lane][pix]
    float* ao = attno + (size_t)b * 1048576 + (size_t)(head * 32 + lane) * 4096;
#pragma unroll
    for (int i = 0; i < 8; i++) {
        int qq = qbase + i; int tr = qq >> 3, tc = qq & 7;
        int pix = (wh * 8 + tr) * 64 + ww * 8 + tc;
        ao[pix] = o_acc[i] / l_i[i];
    }
}

// ---------------------------------------------------------------------------
// Host launcher
// ---------------------------------------------------------------------------
extern "C" void kernel_launch(void* const* d_in, const int* in_sizes, int n_in,
                              void* d_out, int out_size)
{
    const float* x       = (const float*)d_in[0];
    const float* ln1_g   = (const float*)d_in[1];
    const float* ln1_b   = (const float*)d_in[2];
    const float* q_w     = (const float*)d_in[3];
    const float* q_b     = (const float*)d_in[4];
    const float* k_w     = (const float*)d_in[5];
    const float* k_b     = (const float*)d_in[6];
    const float* v_w     = (const float*)d_in[7];
    const float* v_b     = (const float*)d_in[8];
    const float* off1_w  = (const float*)d_in[9];
    const float* off2_w  = (const float*)d_in[10];
    const float* off3_w  = (const float*)d_in[11];
    const float* bn_g    = (const float*)d_in[12];
    const float* bn_b    = (const float*)d_in[13];
    const float* bn_m    = (const float*)d_in[14];
    const float* bn_v    = (const float*)d_in[15];
    const float* off4_w  = (const float*)d_in[16];
    const float* posemb  = (const float*)d_in[17];
    const float* proj_w  = (const float*)d_in[18];
    const float* proj_b  = (const float*)d_in[19];
    const float* ln2_g   = (const float*)d_in[20];
    const float* ln2_b   = (const float*)d_in[21];
    const float* mlp_w1  = (const float*)d_in[22];
    const float* mlp_b1  = (const float*)d_in[23];
    const float* mlp_w2  = (const float*)d_in[24];
    const float* mlp_b2  = (const float*)d_in[25];
    float* out = (float*)d_out;

    float *xa, *qbuf, *o1, *o2, *o3, *grid, *kpart, *vpart, *kkb, *vvb, *attno, *y1, *xm, *hdn;
    cudaGetSymbolAddress((void**)&xa,    g_xa);
    cudaGetSymbolAddress((void**)&qbuf,  g_q);
    cudaGetSymbolAddress((void**)&o1,    g_o1);
    cudaGetSymbolAddress((void**)&o2,    g_o2);
    cudaGetSymbolAddress((void**)&o3,    g_o3);
    cudaGetSymbolAddress((void**)&grid,  g_grid);
    cudaGetSymbolAddress((void**)&kpart, g_kpart);
    cudaGetSymbolAddress((void**)&vpart, g_vpart);
    cudaGetSymbolAddress((void**)&kkb,   g_kk);
    cudaGetSymbolAddress((void**)&vvb,   g_vv);
    cudaGetSymbolAddress((void**)&attno, g_attno);
    cudaGetSymbolAddress((void**)&y1,    g_y1);
    cudaGetSymbolAddress((void**)&xm,    g_xm);
    cudaGetSymbolAddress((void**)&hdn,   g_hdn);

    cudaFuncSetAttribute(attn_kernel, cudaFuncAttributeMaxDynamicSharedMemorySize, 100352);

    // 1. LN1
    ln2d_kernel<<<256, 256>>>(x, ln1_g, ln1_b, xa);

    // 2. q = q_w @ xa + q_b
    sgemm_kernel<<<dim3(64, 4, 2), 256>>>(q_w, xa, qbuf, q_b, nullptr,
        256, 4096, 256, 256, 1048576LL, 1048576LL, 0LL, 1);

    // 3. dw conv chain (q viewed as [4][128][64][64])
    dwconv_kernel<<<512, 256>>>(qbuf, off1_w, o1, 64, 32, 0, nullptr, nullptr, nullptr, nullptr);
    dwconv_kernel<<<512, 256>>>(o1, off2_w, o2, 32, 16, 0, nullptr, nullptr, nullptr, nullptr);
    dwconv_kernel<<<512, 256>>>(o2, off3_w, o3, 16, 8, 1, bn_g, bn_b, bn_m, bn_v);

    // 4. off = off4_w @ o3  (reuse o1 as [4][2048][64])
    sgemm_kernel<<<dim3(1, 32, 4), 256>>>(off4_w, o3, o1, nullptr, nullptr,
        2048, 64, 128, 128, 8192LL, 131072LL, 0LL, 0);

    // 5. sampling grid (pixel coords)
    grid_kernel<<<2048, 256>>>(o1, grid);

    // 6. kpart/vpart: per (b,g) half-projection, output transposed [pix][256]
    for (int bg = 0; bg < 4; bg++) {
        int b = bg >> 1, g = bg & 1;
        const float* Bk = xa + (size_t)b * 1048576 + (size_t)g * 524288;
        sgemm_kernel<<<dim3(64, 4, 1), 256>>>(k_w + g * 128, Bk,
            kpart + (size_t)bg * 1048576, nullptr, nullptr,
            256, 4096, 128, 256, 0LL, 0LL, 0LL, 8);
        sgemm_kernel<<<dim3(64, 4, 1), 256>>>(v_w + g * 128, Bk,
            vpart + (size_t)bg * 1048576, nullptr, nullptr,
            256, 4096, 128, 256, 0LL, 0LL, 0LL, 8);
    }

    // 7. bilinear sampling -> kk, vv
    sample_kernel<<<16384, 256>>>(kpart, vpart, grid, k_b, v_b, kkb, vvb);

    // 8. fused attention
    attn_kernel<<<1024, 256, 98224>>>(qbuf, kkb, vvb, posemb, attno);

    // 9. y1 = x + proj_w @ attno + proj_b
    sgemm_kernel<<<dim3(64, 4, 2), 256>>>(proj_w, attno, y1, proj_b, x,
        256, 4096, 256, 256, 1048576LL, 1048576LL, 1048576LL, 1 | 4);

    // 10. LN2
    ln2d_kernel<<<256, 256>>>(y1, ln2_g, ln2_b, xm);

    // 11. hdn = gelu(mlp_w1 @ xm + b1)
    sgemm_kernel<<<dim3(64, 16, 2), 256>>>(mlp_w1, xm, hdn, mlp_b1, nullptr,
        1024, 4096, 256, 256, 1048576LL, 4194304LL, 0LL, 1 | 2);

    // 12. out = y1 + mlp_w2 @ hdn + b2
    sgemm_kernel<<<dim3(64, 4, 2), 256>>>(mlp_w2, hdn, out, mlp_b2, y1,
        256, 4096, 1024, 1024, 4194304LL, 1048576LL, 1048576LL, 1 | 4);
}